// round 7
// baseline (speedup 1.0000x reference)
#include <cuda_runtime.h>
#include <cuda_fp16.h>

// ---------------- problem constants ----------------
// N=32768, M=8192, D=128, H=128, NH=2 -> hidden 256, HD=64
#define NMAX 32768
#define MMAX 8192
#define EMAX 49152
#define TMAX 294912
#define PMAX (TMAX + NMAX)

// node table cols: [0:256) S(+bsi+bti+bbi) | [256:512) T | [512:768) T2(+bse+bte) | [768:896) M(+bmi)
#define NCC 896
// edge table cols: [0:256) B | [256:512) S | [512:640) M | [640:768) Me(+bme)
#define ECC 768

#define CAPI 128   // smem ex cache per warp (intra)
#define CAPE 64    // smem ex cache per warp (inter)

// ---------------- scratch ----------------
__device__ __half g_node[(size_t)NMAX * NCC];
__device__ __half g_edge[(size_t)MMAX * ECC];
__device__ float  g_accO[(size_t)NMAX * 256];   // [N][256]: intra 0-127, inter 128-255
__device__ float  g_Wn[128 * NCC];
__device__ float  g_We[128 * ECC];
__device__ float  g_Wo[256 * 128];
__device__ float  g_bn[NCC];
__device__ float  g_be[ECC];
__device__ float  g_bo[128];
__device__ float  g_exI[(size_t)PMAX * 2];      // fallback only (deg > CAPI)
__device__ float  g_exE[(size_t)EMAX * 2];      // fallback only (deg > CAPE)
// combined CSR arrays: [0,PMAX) bridge(pair->edges) | [PMAX,+N) tgt(t->pairs) | [PMAX+N,+N) node(n->incidences)
__device__ int    g_cntAll[PMAX + 2 * NMAX];
__device__ int    g_offAll[PMAX + 2 * NMAX];
__device__ int    g_headAll[PMAX + 2 * NMAX];
__device__ int    g_csrB[TMAX];                 // bridge: edge ids
__device__ int    g_csrT[PMAX];                 // tgt: pair ids
__device__ int    g_csrN[EMAX];                 // node: incidence ids
__device__ int    g_partial[1024];

// ---------------- helpers ----------------
__device__ __forceinline__ float gelu_exact(float x) {
    return 0.5f * x * (1.0f + erff(x * 0.70710678118654752f));
}
__device__ __forceinline__ unsigned f2tf32(float x) {
    unsigned r;
    asm("cvt.rna.tf32.f32 %0, %1;" : "=r"(r) : "f"(x));
    return r;
}
__device__ __forceinline__ void load_h8(const __half* p, float* f) {
    uint4 r = *(const uint4*)p;
    float2 v;
    v = __half22float2(*(__half2*)&r.x); f[0] = v.x; f[1] = v.y;
    v = __half22float2(*(__half2*)&r.y); f[2] = v.x; f[3] = v.y;
    v = __half22float2(*(__half2*)&r.z); f[4] = v.x; f[5] = v.y;
    v = __half22float2(*(__half2*)&r.w); f[6] = v.x; f[7] = v.y;
}
__device__ __forceinline__ void load_h4(const __half* p, float* f) {
    uint2 r = *(const uint2*)p;
    float2 v;
    v = __half22float2(*(__half2*)&r.x); f[0] = v.x; f[1] = v.y;
    v = __half22float2(*(__half2*)&r.y); f[2] = v.x; f[3] = v.y;
}

// ---------------- weight/bias packing ----------------
__global__ void pack_weights(const float* __restrict__ Wsi, const float* __restrict__ Wti,
                             const float* __restrict__ Wte, const float* __restrict__ Wmi,
                             const float* __restrict__ Wbi, const float* __restrict__ Wse,
                             const float* __restrict__ Wme,
                             const float* __restrict__ Woi, const float* __restrict__ Woe,
                             const float* __restrict__ bsi, const float* __restrict__ bti,
                             const float* __restrict__ bbi, const float* __restrict__ bse,
                             const float* __restrict__ bte, const float* __restrict__ bmi,
                             const float* __restrict__ bme, const float* __restrict__ boi,
                             const float* __restrict__ boe) {
    int i = blockIdx.x * blockDim.x + threadIdx.x;
    if (i < 128 * NCC) {
        int r = i / NCC, c = i % NCC;
        float v;
        if (c < 256) v = Wsi[r * 256 + c];
        else if (c < 512) v = Wti[r * 256 + (c - 256)];
        else if (c < 768) v = Wte[r * 256 + (c - 512)];
        else v = Wmi[r * 128 + (c - 768)];            // Wmi top half
        g_Wn[i] = v;
    }
    if (i < 128 * ECC) {
        int r = i / ECC, c = i % ECC;
        float v;
        if (c < 256) v = Wbi[r * 256 + c];
        else if (c < 512) v = Wse[r * 256 + (c - 256)];
        else if (c < 640) v = Wmi[(128 + r) * 128 + (c - 512)];  // Wmi bottom half
        else v = Wme[r * 128 + (c - 640)];
        g_We[i] = v;
    }
    if (i < 256 * 128) {
        int r = i / 128, c = i % 128;
        g_Wo[i] = (r < 128) ? Woi[r * 128 + c] : Woe[(r - 128) * 128 + c];
    }
    if (i < NCC) {
        float v;
        if (i < 256) v = bsi[i] + bti[i] + bbi[i];
        else if (i < 512) v = 0.f;
        else if (i < 768) v = bse[i - 512] + bte[i - 512];
        else v = bmi[i - 768];
        g_bn[i] = v;
    }
    if (i < ECC) g_be[i] = (i >= 640) ? bme[i - 640] : 0.f;
    if (i < 128) g_bo[i] = boi[i] + boe[i];
}

// ---------------- tf32 tensor-core GEMM, CTA tile 128x128, K-looped ---------
#define AS_PITCH 132
#define WS_PITCH 136
#define GEMM_SMEM ((128 * AS_PITCH + 128 * WS_PITCH) * 4)

template <bool HALF_OUT>
__global__ void gemm_tf32_t(const float* __restrict__ A, const float* __restrict__ W,
                            const float* __restrict__ bias, void* __restrict__ Cv,
                            int KK, int CC) {
    extern __shared__ unsigned sh[];
    unsigned* As = sh;
    unsigned* Ws = sh + 128 * AS_PITCH;
    const int tid = threadIdx.x;
    const int lane = tid & 31;
    const int warp = tid >> 5;
    const int wm = warp & 3;
    const int wn = warp >> 2;
    const long r0 = (long)blockIdx.y * 128;
    const int  c0 = blockIdx.x * 128;
    const int gid = lane >> 2;
    const int tig = lane & 3;

    float c[2][8][4];
#pragma unroll
    for (int mt = 0; mt < 2; mt++)
#pragma unroll
        for (int nt = 0; nt < 8; nt++)
#pragma unroll
            for (int q = 0; q < 4; q++) c[mt][nt][q] = 0.f;

    for (int kb = 0; kb < KK; kb += 128) {
        if (kb) __syncthreads();
#pragma unroll
        for (int i = 0; i < 16; i++) {
            int idx = tid + i * 256;
            int row = idx >> 5;
            int c4 = idx & 31;
            float4 v = *(const float4*)(A + (r0 + row) * KK + kb + c4 * 4);
            unsigned* dst = As + row * AS_PITCH + c4 * 4;
            dst[0] = f2tf32(v.x); dst[1] = f2tf32(v.y);
            dst[2] = f2tf32(v.z); dst[3] = f2tf32(v.w);
        }
#pragma unroll
        for (int i = 0; i < 16; i++) {
            int idx = tid + i * 256;
            int row = idx >> 5;
            int c4 = idx & 31;
            float4 v = *(const float4*)(W + (long)(kb + row) * CC + c0 + c4 * 4);
            unsigned* dst = Ws + row * WS_PITCH + c4 * 4;
            dst[0] = f2tf32(v.x); dst[1] = f2tf32(v.y);
            dst[2] = f2tf32(v.z); dst[3] = f2tf32(v.w);
        }
        __syncthreads();

        const int arow = wm * 32 + gid;
        const int bcol = wn * 64 + gid;
#pragma unroll
        for (int k0 = 0; k0 < 128; k0 += 8) {
            unsigned a[2][4], b[8][2];
#pragma unroll
            for (int mt = 0; mt < 2; mt++) {
                const unsigned* ap = As + (arow + mt * 16) * AS_PITCH + k0 + tig;
                a[mt][0] = ap[0];
                a[mt][1] = ap[8 * AS_PITCH];
                a[mt][2] = ap[4];
                a[mt][3] = ap[8 * AS_PITCH + 4];
            }
#pragma unroll
            for (int nt = 0; nt < 8; nt++) {
                b[nt][0] = Ws[(k0 + tig) * WS_PITCH + bcol + nt * 8];
                b[nt][1] = Ws[(k0 + tig + 4) * WS_PITCH + bcol + nt * 8];
            }
#pragma unroll
            for (int mt = 0; mt < 2; mt++)
#pragma unroll
                for (int nt = 0; nt < 8; nt++)
                    asm volatile(
                        "mma.sync.aligned.m16n8k8.row.col.f32.tf32.tf32.f32 "
                        "{%0,%1,%2,%3}, {%4,%5,%6,%7}, {%8,%9}, {%0,%1,%2,%3};"
                        : "+f"(c[mt][nt][0]), "+f"(c[mt][nt][1]),
                          "+f"(c[mt][nt][2]), "+f"(c[mt][nt][3])
                        : "r"(a[mt][0]), "r"(a[mt][1]), "r"(a[mt][2]), "r"(a[mt][3]),
                          "r"(b[nt][0]), "r"(b[nt][1]));
        }
    }

#pragma unroll
    for (int mt = 0; mt < 2; mt++) {
        long r = r0 + wm * 32 + mt * 16 + gid;
#pragma unroll
        for (int nt = 0; nt < 8; nt++) {
            int col = c0 + wn * 64 + nt * 8 + 2 * tig;
            float2 bv = bias ? *(const float2*)(bias + col) : make_float2(0.f, 0.f);
            float x0 = c[mt][nt][0] + bv.x, y0 = c[mt][nt][1] + bv.y;
            float x1 = c[mt][nt][2] + bv.x, y1 = c[mt][nt][3] + bv.y;
            if (HALF_OUT) {
                __half* C = (__half*)Cv;
                *(__half2*)(C + r * CC + col) = __floats2half2_rn(x0, y0);
                *(__half2*)(C + (r + 8) * CC + col) = __floats2half2_rn(x1, y1);
            } else {
                float* C = (float*)Cv;
                *(float2*)(C + r * CC + col) = make_float2(x0, y0);
                *(float2*)(C + (r + 8) * CC + col) = make_float2(x1, y1);
            }
        }
    }
}

// ---------------- combined CSR build (3 CSRs in one set of passes) ----------
__global__ void hist_all(const int* __restrict__ tri_pair, int T,
                         const int* __restrict__ pair_tgt, int P,
                         const int* __restrict__ inc_node, int E) {
    int i = blockIdx.x * blockDim.x + threadIdx.x;
    if (i < T) atomicAdd(&g_cntAll[tri_pair[i]], 1);
    if (i < P) atomicAdd(&g_cntAll[PMAX + pair_tgt[i]], 1);
    if (i < E) atomicAdd(&g_cntAll[PMAX + NMAX + inc_node[i]], 1);
}

// region mapping: blocks [0,nb0) -> bridge (len P, base 0, partials@0)
//                 [nb0, nb0+nbN) -> tgt   (len N, base PMAX, partials@128)
//                 [nb0+nbN, +nbN) -> node (len N, base PMAX+NMAX, partials@144)
__global__ void scan_block_all(int P, int N, int nb0, int nbN) {
    __shared__ int wsum[32];
    int b = blockIdx.x;
    int base, len, pbase, lb;
    if (b < nb0) { base = 0; len = P; pbase = 0; lb = b; }
    else if (b < nb0 + nbN) { base = PMAX; len = N; pbase = 128; lb = b - nb0; }
    else { base = PMAX + NMAX; len = N; pbase = 144; lb = b - nb0 - nbN; }

    int tid = threadIdx.x;
    int i0 = lb * 4096 + tid * 4;
    int v[4], s = 0;
#pragma unroll
    for (int q = 0; q < 4; q++) {
        v[q] = (i0 + q < len) ? g_cntAll[base + i0 + q] : 0;
        s += v[q];
    }
    int lane = tid & 31, wid = tid >> 5;
    int x = s;
#pragma unroll
    for (int o = 1; o < 32; o <<= 1) {
        int y = __shfl_up_sync(0xffffffffu, x, o);
        if (lane >= o) x += y;
    }
    if (lane == 31) wsum[wid] = x;
    __syncthreads();
    if (wid == 0) {
        int w = wsum[lane];
#pragma unroll
        for (int o = 1; o < 32; o <<= 1) {
            int y = __shfl_up_sync(0xffffffffu, w, o);
            if (lane >= o) w += y;
        }
        wsum[lane] = w;
    }
    __syncthreads();
    int excl = x - s + (wid > 0 ? wsum[wid - 1] : 0);
    int run = excl;
#pragma unroll
    for (int q = 0; q < 4; q++) {
        if (i0 + q < len) g_offAll[base + i0 + q] = run;
        run += v[q];
    }
    if (tid == 1023) g_partial[pbase + lb] = wsum[31];
}

__global__ void scan_partials_all(int nb0, int nbN) {
    int tid = threadIdx.x;
    if (tid == 0) {
        int s = 0;
        for (int i = 0; i < nb0; i++) { int v = g_partial[i]; g_partial[i] = s; s += v; }
    } else if (tid == 1) {
        int s = 0;
        for (int i = 0; i < nbN; i++) { int v = g_partial[128 + i]; g_partial[128 + i] = s; s += v; }
    } else if (tid == 2) {
        int s = 0;
        for (int i = 0; i < nbN; i++) { int v = g_partial[144 + i]; g_partial[144 + i] = s; s += v; }
    }
}

__global__ void add_off_all(int P, int N) {
    int i = blockIdx.x * blockDim.x + threadIdx.x;
    int idx, pseg, blk;
    if (i < P) { idx = i; pseg = 0; blk = i >> 12; }
    else if (i < P + N) { int j = i - P; idx = PMAX + j; pseg = 128; blk = j >> 12; }
    else if (i < P + 2 * N) { int j = i - P - N; idx = PMAX + NMAX + j; pseg = 144; blk = j >> 12; }
    else return;
    int o = g_offAll[idx] + g_partial[pseg + blk];
    g_offAll[idx] = o;
    g_headAll[idx] = o;
}

__global__ void fill_all(const int* __restrict__ tri_pair, const int* __restrict__ tri_edge, int T,
                         const int* __restrict__ pair_tgt, int P,
                         const int* __restrict__ inc_node, int E) {
    int i = blockIdx.x * blockDim.x + threadIdx.x;
    if (i < T) {
        int pos = atomicAdd(&g_headAll[tri_pair[i]], 1);
        g_csrB[pos] = tri_edge[i];
    }
    if (i < P) {
        int pos = atomicAdd(&g_headAll[PMAX + pair_tgt[i]], 1);
        g_csrT[pos] = i;
    }
    if (i < E) {
        int pos = atomicAdd(&g_headAll[PMAX + NMAX + inc_node[i]], 1);
        g_csrN[pos] = i;
    }
}

// ---------------- fused intra attention: warp per TARGET node ---------------
__global__ void intra_fused(const int* __restrict__ pair_src,
                            const float* __restrict__ pair_cnt,
                            const float* __restrict__ ai, int N) {
    __shared__ float s_ex[8][2 * CAPI];
    int w = (int)(((long)blockIdx.x * blockDim.x + threadIdx.x) >> 5);
    int lane = threadIdx.x & 31;
    int wib = threadIdx.x >> 5;
    if (w >= N) return;
    const int t = w;
    const int deg = g_cntAll[PMAX + t];
    const int toff = g_offAll[PMAX + t];

    float tv[8];
    load_h8(g_node + (size_t)t * NCC + 256 + lane * 8, tv);   // T row, loaded ONCE
    float4 a0 = *(const float4*)(ai + lane * 8);
    float4 a1 = *(const float4*)(ai + lane * 8 + 4);
    float av[8] = {a0.x, a0.y, a0.z, a0.w, a1.x, a1.y, a1.z, a1.w};

    const bool fits = (deg <= CAPI);
    float den0 = 0.f, den1 = 0.f;

    for (int j = 0; j < deg; j++) {
        int p = __ldg(&g_csrT[toff + j]);
        int s = __ldg(&pair_src[p]);
        float inv = 1.0f / __ldg(&pair_cnt[p]);
        int bdeg = g_cntAll[p];
        int boff = g_offAll[p];
        float u[8];
        load_h8(g_node + (size_t)s * NCC + lane * 8, u);      // S row (+biases)
        float ab[8] = {0.f, 0.f, 0.f, 0.f, 0.f, 0.f, 0.f, 0.f};
        for (int k = 0; k < bdeg; k++) {
            int e = __ldg(&g_csrB[boff + k]);
            float bv[8];
            load_h8(g_edge + (size_t)e * ECC + lane * 8, bv); // B row
#pragma unroll
            for (int q = 0; q < 8; q++) ab[q] += bv[q];
        }
        float partial = 0.f;
#pragma unroll
        for (int q = 0; q < 8; q++)
            partial += gelu_exact(u[q] + tv[q] + ab[q] * inv) * av[q];
#pragma unroll
        for (int o = 8; o; o >>= 1) partial += __shfl_down_sync(0xffffffffu, partial, o);
        float l0 = __shfl_sync(0xffffffffu, partial, 0);
        float l1 = __shfl_sync(0xffffffffu, partial, 16);
        float e0 = expf(l0), e1 = expf(l1);
        den0 += e0; den1 += e1;
        if (fits) {
            if (lane == 0) { s_ex[wib][2 * j] = e0; s_ex[wib][2 * j + 1] = e1; }
        } else if (lane == 0) {
            g_exI[(size_t)p * 2] = e0;
            g_exI[(size_t)p * 2 + 1] = e1;
        }
    }
    __syncwarp();

    const int h = lane >> 4;
    const float denh = h ? den1 : den0;
    float ac0 = 0.f, ac1 = 0.f, ac2 = 0.f, ac3 = 0.f;

    for (int j = 0; j < deg; j++) {
        int p = __ldg(&g_csrT[toff + j]);
        int s = __ldg(&pair_src[p]);
        float inv = 1.0f / __ldg(&pair_cnt[p]);
        int bdeg = g_cntAll[p];
        int boff = g_offAll[p];
        float m[4];
        load_h4(g_node + (size_t)s * NCC + 768 + lane * 4, m);  // M row (+bmi)
        float am[4] = {0.f, 0.f, 0.f, 0.f};
        for (int k = 0; k < bdeg; k++) {
            int e = __ldg(&g_csrB[boff + k]);
            float mv[4];
            load_h4(g_edge + (size_t)e * ECC + 512 + lane * 4, mv);
#pragma unroll
            for (int q = 0; q < 4; q++) am[q] += mv[q];
        }
        float exh;
        if (fits) {
            exh = s_ex[wib][2 * j + h];
        } else {
            float t0 = 0.f, t1 = 0.f;
            if (lane == 0) { t0 = g_exI[(size_t)p * 2]; t1 = g_exI[(size_t)p * 2 + 1]; }
            t0 = __shfl_sync(0xffffffffu, t0, 0);
            t1 = __shfl_sync(0xffffffffu, t1, 0);
            exh = h ? t1 : t0;
        }
        float sc = exh / denh;
        ac0 = fmaf(m[0] + am[0] * inv, sc, ac0);
        ac1 = fmaf(m[1] + am[1] * inv, sc, ac1);
        ac2 = fmaf(m[2] + am[2] * inv, sc, ac2);
        ac3 = fmaf(m[3] + am[3] * inv, sc, ac3);
    }
    *(float4*)(g_accO + (size_t)t * 256 + lane * 4) = make_float4(ac0, ac1, ac2, ac3);
}

// ---------------- fused inter attention: warp per node ----------------------
__global__ void inter_fused(const int* __restrict__ inc_edge,
                            const float* __restrict__ ae, int N) {
    __shared__ float s_ex[8][2 * CAPE];
    int w = (int)(((long)blockIdx.x * blockDim.x + threadIdx.x) >> 5);
    int lane = threadIdx.x & 31;
    int wib = threadIdx.x >> 5;
    if (w >= N) return;
    const int n = w;
    const int deg = g_cntAll[PMAX + NMAX + n];
    const int noff = g_offAll[PMAX + NMAX + n];

    if (deg == 0) {
        *(float4*)(g_accO + (size_t)n * 256 + 128 + lane * 4) = make_float4(0.f, 0.f, 0.f, 0.f);
        return;
    }

    float tv[8];
    load_h8(g_node + (size_t)n * NCC + 512 + lane * 8, tv);   // T2 row (+biases)
    float4 a0 = *(const float4*)(ae + lane * 8);
    float4 a1 = *(const float4*)(ae + lane * 8 + 4);
    float av[8] = {a0.x, a0.y, a0.z, a0.w, a1.x, a1.y, a1.z, a1.w};

    const bool fits = (deg <= CAPE);
    float den0 = 0.f, den1 = 0.f;

    for (int j = 0; j < deg; j++) {
        int i = __ldg(&g_csrN[noff + j]);
        int e = __ldg(&inc_edge[i]);
        float u[8];
        load_h8(g_edge + (size_t)e * ECC + 256 + lane * 8, u);  // S(e) row
        float partial = 0.f;
#pragma unroll
        for (int q = 0; q < 8; q++)
            partial += gelu_exact(u[q] + tv[q]) * av[q];
#pragma unroll
        for (int o = 8; o; o >>= 1) partial += __shfl_down_sync(0xffffffffu, partial, o);
        float l0 = __shfl_sync(0xffffffffu, partial, 0);
        float l1 = __shfl_sync(0xffffffffu, partial, 16);
        float e0 = expf(l0), e1 = expf(l1);
        den0 += e0; den1 += e1;
        if (fits) {
            if (lane == 0) { s_ex[wib][2 * j] = e0; s_ex[wib][2 * j + 1] = e1; }
        } else if (lane == 0) {
            g_exE[(size_t)i * 2] = e0;
            g_exE[(size_t)i * 2 + 1] = e1;
        }
    }
    __syncwarp();

    const int h = lane >> 4;
    const float denh = h ? den1 : den0;
    float ac0 = 0.f, ac1 = 0.f, ac2 = 0.f, ac3 = 0.f;

    for (int j = 0; j < deg; j++) {
        int i = __ldg(&g_csrN[noff + j]);
        int e = __ldg(&inc_edge[i]);
        float m[4];
        load_h4(g_edge + (size_t)e * ECC + 640 + lane * 4, m);  // Me row (+bme)
        float exh;
        if (fits) {
            exh = s_ex[wib][2 * j + h];
        } else {
            float t0 = 0.f, t1 = 0.f;
            if (lane == 0) { t0 = g_exE[(size_t)i * 2]; t1 = g_exE[(size_t)i * 2 + 1]; }
            t0 = __shfl_sync(0xffffffffu, t0, 0);
            t1 = __shfl_sync(0xffffffffu, t1, 0);
            exh = h ? t1 : t0;
        }
        float sc = exh / denh;
        ac0 = fmaf(m[0], sc, ac0);
        ac1 = fmaf(m[1], sc, ac1);
        ac2 = fmaf(m[2], sc, ac2);
        ac3 = fmaf(m[3], sc, ac3);
    }
    *(float4*)(g_accO + (size_t)n * 256 + 128 + lane * 4) = make_float4(ac0, ac1, ac2, ac3);
}

// ---------------- launch ----------------
extern "C" void kernel_launch(void* const* d_in, const int* in_sizes, int n_in,
                              void* d_out, int out_size) {
    const float* node_feat = (const float*)d_in[0];
    const float* edge_feat = (const float*)d_in[1];
    const int*   inc_node  = (const int*)d_in[2];
    const int*   inc_edge  = (const int*)d_in[3];
    const int*   pair_src  = (const int*)d_in[4];
    const int*   pair_tgt  = (const int*)d_in[5];
    const float* pair_cnt  = (const float*)d_in[6];
    const int*   tri_pair  = (const int*)d_in[7];
    const int*   tri_edge  = (const int*)d_in[8];
    const float* Wsi = (const float*)d_in[9];
    const float* bsi = (const float*)d_in[10];
    const float* Wti = (const float*)d_in[11];
    const float* bti = (const float*)d_in[12];
    const float* Wbi = (const float*)d_in[13];
    const float* bbi = (const float*)d_in[14];
    const float* ai  = (const float*)d_in[15];
    const float* Wmi = (const float*)d_in[16];
    const float* bmi = (const float*)d_in[17];
    const float* Woi = (const float*)d_in[18];
    const float* boi = (const float*)d_in[19];
    const float* Wse = (const float*)d_in[20];
    const float* bse = (const float*)d_in[21];
    const float* Wte = (const float*)d_in[22];
    const float* bte = (const float*)d_in[23];
    const float* ae  = (const float*)d_in[24];
    const float* Wme = (const float*)d_in[25];
    const float* bme = (const float*)d_in[26];
    const float* Woe = (const float*)d_in[27];
    const float* boe = (const float*)d_in[28];

    const int N = in_sizes[0] / 128;
    const int M = in_sizes[1] / 128;
    const int E = in_sizes[2];
    const int P = in_sizes[4];
    const int T = in_sizes[7];
    if (N > NMAX || M > MMAX || E > EMAX || P > PMAX || T > TMAX) return;

    void *pNode, *pEdge, *pAccO, *pWn, *pWe, *pWo, *pBn, *pBe, *pBo, *pCntAll;
    cudaGetSymbolAddress(&pNode, g_node);
    cudaGetSymbolAddress(&pEdge, g_edge);
    cudaGetSymbolAddress(&pAccO, g_accO);
    cudaGetSymbolAddress(&pWn, g_Wn);
    cudaGetSymbolAddress(&pWe, g_We);
    cudaGetSymbolAddress(&pWo, g_Wo);
    cudaGetSymbolAddress(&pBn, g_bn);
    cudaGetSymbolAddress(&pBe, g_be);
    cudaGetSymbolAddress(&pBo, g_bo);
    cudaGetSymbolAddress(&pCntAll, g_cntAll);

    cudaFuncSetAttribute(gemm_tf32_t<true>, cudaFuncAttributeMaxDynamicSharedMemorySize, GEMM_SMEM);
    cudaFuncSetAttribute(gemm_tf32_t<false>, cudaFuncAttributeMaxDynamicSharedMemorySize, GEMM_SMEM);

    float* out = (float*)d_out;

    // 1) zero all CSR counters in one memset
    cudaMemsetAsync(pCntAll, 0, (size_t)(PMAX + 2 * NMAX) * sizeof(int), 0);

    // 2) pack weights / biases
    pack_weights<<<(128 * NCC + 255) / 256, 256>>>(Wsi, Wti, Wte, Wmi, Wbi, Wse, Wme, Woi, Woe,
                                                   bsi, bti, bbi, bse, bte, bmi, bme, boi, boe);

    // 3) projection GEMMs -> combined fp16 tables (biases baked in)
    gemm_tf32_t<true><<<dim3(NCC / 128, N / 128), 256, GEMM_SMEM>>>(
        node_feat, (const float*)pWn, (const float*)pBn, pNode, 128, NCC);
    gemm_tf32_t<true><<<dim3(ECC / 128, M / 128), 256, GEMM_SMEM>>>(
        edge_feat, (const float*)pWe, (const float*)pBe, pEdge, 128, ECC);

    // 4) combined CSR build (bridge, tgt, node)
    int mx = T > P ? T : P;
    if (E > mx) mx = E;
    int nb0 = (P + 4095) / 4096;
    int nbN = (N + 4095) / 4096;
    hist_all<<<(mx + 255) / 256, 256>>>(tri_pair, T, pair_tgt, P, inc_node, E);
    scan_block_all<<<nb0 + 2 * nbN, 1024>>>(P, N, nb0, nbN);
    scan_partials_all<<<1, 32>>>(nb0, nbN);
    add_off_all<<<(P + 2 * N + 255) / 256, 256>>>(P, N);
    fill_all<<<(mx + 255) / 256, 256>>>(tri_pair, tri_edge, T, pair_tgt, P, inc_node, E);

    // 5) fused attention passes (no atomics, plain stores into accO)
    int nwb = (int)(((long)N * 32 + 255) / 256);
    intra_fused<<<nwb, 256>>>(pair_src, pair_cnt, ai, N);
    inter_fused<<<nwb, 256>>>(inc_edge, ae, N);

    // 6) fused output projection: out = [accI|accE] @ [Woi;Woe] + (boi+boe)
    gemm_tf32_t<false><<<dim3(1, N / 128), 256, GEMM_SMEM>>>(
        (const float*)pAccO, (const float*)pWo, (const float*)pBo, out, 256, 128);
}

// round 9
// speedup vs baseline: 1.3505x; 1.3505x over previous
#include <cuda_runtime.h>
#include <cuda_fp16.h>

// ---------------- problem constants ----------------
// N=32768, M=8192, D=128, H=128, NH=2 -> hidden 256, HD=64
#define NMAX 32768
#define MMAX 8192
#define EMAX 49152
#define TMAX 294912
#define PMAX (TMAX + NMAX)

// node table cols: [0:256) S(+bsi+bti+bbi) | [256:512) T | [512:768) T2(+bse+bte) | [768:896) M(+bmi)
#define NCC 896
// edge table cols: [0:256) B | [256:512) S | [512:640) M | [640:768) Me(+bme)
#define ECC 768

// ---------------- scratch ----------------
__device__ __half g_node[(size_t)NMAX * NCC];
__device__ __half g_edge[(size_t)MMAX * ECC];
__device__ float  g_accO[(size_t)NMAX * 256];   // [N][256]: intra 0-127, inter 128-255
__device__ float  g_Wn[128 * NCC];
__device__ float  g_We[128 * ECC];
__device__ float  g_Wo[256 * 128];
__device__ float  g_bn[NCC];
__device__ float  g_be[ECC];
__device__ float  g_bo[128];
__device__ float  g_denomI[NMAX * 2];
__device__ float  g_denomE[NMAX * 2];
// CSR: pair -> bridging edges
__device__ int    g_cnt[PMAX];
__device__ int    g_off[PMAX];
__device__ int    g_head[PMAX];
__device__ int    g_csr[TMAX];
__device__ int    g_partial[1024];

// ---------------- helpers ----------------
__device__ __forceinline__ float gelu_exact(float x) {
    return 0.5f * x * (1.0f + erff(x * 0.70710678118654752f));
}
__device__ __forceinline__ void red4(float* addr, float a, float b, float c, float d) {
    asm volatile("red.global.add.v4.f32 [%0], {%1,%2,%3,%4};"
                 :: "l"(addr), "f"(a), "f"(b), "f"(c), "f"(d) : "memory");
}
__device__ __forceinline__ unsigned f2tf32(float x) {
    unsigned r;
    asm("cvt.rna.tf32.f32 %0, %1;" : "=r"(r) : "f"(x));
    return r;
}
__device__ __forceinline__ void load_h8(const __half* p, float* f) {
    uint4 r = *(const uint4*)p;
    float2 v;
    v = __half22float2(*(__half2*)&r.x); f[0] = v.x; f[1] = v.y;
    v = __half22float2(*(__half2*)&r.y); f[2] = v.x; f[3] = v.y;
    v = __half22float2(*(__half2*)&r.z); f[4] = v.x; f[5] = v.y;
    v = __half22float2(*(__half2*)&r.w); f[6] = v.x; f[7] = v.y;
}
__device__ __forceinline__ void load_h4(const __half* p, float* f) {
    uint2 r = *(const uint2*)p;
    float2 v;
    v = __half22float2(*(__half2*)&r.x); f[0] = v.x; f[1] = v.y;
    v = __half22float2(*(__half2*)&r.y); f[2] = v.x; f[3] = v.y;
}

// ---------------- weight/bias packing ----------------
__global__ void pack_weights(const float* __restrict__ Wsi, const float* __restrict__ Wti,
                             const float* __restrict__ Wte, const float* __restrict__ Wmi,
                             const float* __restrict__ Wbi, const float* __restrict__ Wse,
                             const float* __restrict__ Wme,
                             const float* __restrict__ Woi, const float* __restrict__ Woe,
                             const float* __restrict__ bsi, const float* __restrict__ bti,
                             const float* __restrict__ bbi, const float* __restrict__ bse,
                             const float* __restrict__ bte, const float* __restrict__ bmi,
                             const float* __restrict__ bme, const float* __restrict__ boi,
                             const float* __restrict__ boe) {
    int i = blockIdx.x * blockDim.x + threadIdx.x;
    if (i < 128 * NCC) {
        int r = i / NCC, c = i % NCC;
        float v;
        if (c < 256) v = Wsi[r * 256 + c];
        else if (c < 512) v = Wti[r * 256 + (c - 256)];
        else if (c < 768) v = Wte[r * 256 + (c - 512)];
        else v = Wmi[r * 128 + (c - 768)];            // Wmi top half
        g_Wn[i] = v;
    }
    if (i < 128 * ECC) {
        int r = i / ECC, c = i % ECC;
        float v;
        if (c < 256) v = Wbi[r * 256 + c];
        else if (c < 512) v = Wse[r * 256 + (c - 256)];
        else if (c < 640) v = Wmi[(128 + r) * 128 + (c - 512)];  // Wmi bottom half
        else v = Wme[r * 128 + (c - 640)];
        g_We[i] = v;
    }
    if (i < 256 * 128) {
        int r = i / 128, c = i % 128;
        g_Wo[i] = (r < 128) ? Woi[r * 128 + c] : Woe[(r - 128) * 128 + c];
    }
    if (i < NCC) {
        float v;
        if (i < 256) v = bsi[i] + bti[i] + bbi[i];
        else if (i < 512) v = 0.f;
        else if (i < 768) v = bse[i - 512] + bte[i - 512];
        else v = bmi[i - 768];
        g_bn[i] = v;
    }
    if (i < ECC) g_be[i] = (i >= 640) ? bme[i - 640] : 0.f;
    if (i < 128) g_bo[i] = boi[i] + boe[i];
}

// ---------------- tf32 tensor-core GEMM, CTA tile 128x128, K-looped ---------
#define AS_PITCH 132
#define WS_PITCH 136
#define GEMM_SMEM ((128 * AS_PITCH + 128 * WS_PITCH) * 4)

template <bool HALF_OUT>
__global__ void gemm_tf32_t(const float* __restrict__ A, const float* __restrict__ W,
                            const float* __restrict__ bias, void* __restrict__ Cv,
                            int KK, int CC) {
    extern __shared__ unsigned sh[];
    unsigned* As = sh;
    unsigned* Ws = sh + 128 * AS_PITCH;
    const int tid = threadIdx.x;
    const int lane = tid & 31;
    const int warp = tid >> 5;
    const int wm = warp & 3;
    const int wn = warp >> 2;
    const long r0 = (long)blockIdx.y * 128;
    const int  c0 = blockIdx.x * 128;
    const int gid = lane >> 2;
    const int tig = lane & 3;

    float c[2][8][4];
#pragma unroll
    for (int mt = 0; mt < 2; mt++)
#pragma unroll
        for (int nt = 0; nt < 8; nt++)
#pragma unroll
            for (int q = 0; q < 4; q++) c[mt][nt][q] = 0.f;

    for (int kb = 0; kb < KK; kb += 128) {
        if (kb) __syncthreads();
#pragma unroll
        for (int i = 0; i < 16; i++) {
            int idx = tid + i * 256;
            int row = idx >> 5;
            int c4 = idx & 31;
            float4 v = *(const float4*)(A + (r0 + row) * KK + kb + c4 * 4);
            unsigned* dst = As + row * AS_PITCH + c4 * 4;
            dst[0] = f2tf32(v.x); dst[1] = f2tf32(v.y);
            dst[2] = f2tf32(v.z); dst[3] = f2tf32(v.w);
        }
#pragma unroll
        for (int i = 0; i < 16; i++) {
            int idx = tid + i * 256;
            int row = idx >> 5;
            int c4 = idx & 31;
            float4 v = *(const float4*)(W + (long)(kb + row) * CC + c0 + c4 * 4);
            unsigned* dst = Ws + row * WS_PITCH + c4 * 4;
            dst[0] = f2tf32(v.x); dst[1] = f2tf32(v.y);
            dst[2] = f2tf32(v.z); dst[3] = f2tf32(v.w);
        }
        __syncthreads();

        const int arow = wm * 32 + gid;
        const int bcol = wn * 64 + gid;
#pragma unroll
        for (int k0 = 0; k0 < 128; k0 += 8) {
            unsigned a[2][4], b[8][2];
#pragma unroll
            for (int mt = 0; mt < 2; mt++) {
                const unsigned* ap = As + (arow + mt * 16) * AS_PITCH + k0 + tig;
                a[mt][0] = ap[0];
                a[mt][1] = ap[8 * AS_PITCH];
                a[mt][2] = ap[4];
                a[mt][3] = ap[8 * AS_PITCH + 4];
            }
#pragma unroll
            for (int nt = 0; nt < 8; nt++) {
                b[nt][0] = Ws[(k0 + tig) * WS_PITCH + bcol + nt * 8];
                b[nt][1] = Ws[(k0 + tig + 4) * WS_PITCH + bcol + nt * 8];
            }
#pragma unroll
            for (int mt = 0; mt < 2; mt++)
#pragma unroll
                for (int nt = 0; nt < 8; nt++)
                    asm volatile(
                        "mma.sync.aligned.m16n8k8.row.col.f32.tf32.tf32.f32 "
                        "{%0,%1,%2,%3}, {%4,%5,%6,%7}, {%8,%9}, {%0,%1,%2,%3};"
                        : "+f"(c[mt][nt][0]), "+f"(c[mt][nt][1]),
                          "+f"(c[mt][nt][2]), "+f"(c[mt][nt][3])
                        : "r"(a[mt][0]), "r"(a[mt][1]), "r"(a[mt][2]), "r"(a[mt][3]),
                          "r"(b[nt][0]), "r"(b[nt][1]));
        }
    }

#pragma unroll
    for (int mt = 0; mt < 2; mt++) {
        long r = r0 + wm * 32 + mt * 16 + gid;
#pragma unroll
        for (int nt = 0; nt < 8; nt++) {
            int col = c0 + wn * 64 + nt * 8 + 2 * tig;
            float2 bv = bias ? *(const float2*)(bias + col) : make_float2(0.f, 0.f);
            float x0 = c[mt][nt][0] + bv.x, y0 = c[mt][nt][1] + bv.y;
            float x1 = c[mt][nt][2] + bv.x, y1 = c[mt][nt][3] + bv.y;
            if (HALF_OUT) {
                __half* C = (__half*)Cv;
                *(__half2*)(C + r * CC + col) = __floats2half2_rn(x0, y0);
                *(__half2*)(C + (r + 8) * CC + col) = __floats2half2_rn(x1, y1);
            } else {
                float* C = (float*)Cv;
                *(float2*)(C + r * CC + col) = make_float2(x0, y0);
                *(float2*)(C + (r + 8) * CC + col) = make_float2(x1, y1);
            }
        }
    }
}

// ---------------- CSR build: pair -> bridging edge list ---------------------
__global__ void csr_hist(const int* __restrict__ tri_pair, int T) {
    int i = blockIdx.x * blockDim.x + threadIdx.x;
    if (i < T) atomicAdd(&g_cnt[tri_pair[i]], 1);
}

__global__ void csr_scan_block(int P) {
    __shared__ int wsum[32];
    int tid = threadIdx.x;
    int base = blockIdx.x * 4096 + tid * 4;
    int v[4], s = 0;
#pragma unroll
    for (int q = 0; q < 4; q++) {
        v[q] = (base + q < P) ? g_cnt[base + q] : 0;
        s += v[q];
    }
    int lane = tid & 31, wid = tid >> 5;
    int x = s;
#pragma unroll
    for (int o = 1; o < 32; o <<= 1) {
        int y = __shfl_up_sync(0xffffffffu, x, o);
        if (lane >= o) x += y;
    }
    if (lane == 31) wsum[wid] = x;
    __syncthreads();
    if (wid == 0) {
        int w = wsum[lane];
#pragma unroll
        for (int o = 1; o < 32; o <<= 1) {
            int y = __shfl_up_sync(0xffffffffu, w, o);
            if (lane >= o) w += y;
        }
        wsum[lane] = w;
    }
    __syncthreads();
    int excl = x - s + (wid > 0 ? wsum[wid - 1] : 0);
    int run = excl;
#pragma unroll
    for (int q = 0; q < 4; q++) {
        if (base + q < P) g_off[base + q] = run;
        run += v[q];
    }
    if (tid == 1023) g_partial[blockIdx.x] = wsum[31];
}

__global__ void csr_scan_partials(int nb) {
    __shared__ int wsum[32];
    int tid = threadIdx.x;  // 1024
    int v = (tid < nb) ? g_partial[tid] : 0;
    int lane = tid & 31, wid = tid >> 5;
    int x = v;
#pragma unroll
    for (int o = 1; o < 32; o <<= 1) {
        int y = __shfl_up_sync(0xffffffffu, x, o);
        if (lane >= o) x += y;
    }
    if (lane == 31) wsum[wid] = x;
    __syncthreads();
    if (wid == 0) {
        int w = wsum[lane];
#pragma unroll
        for (int o = 1; o < 32; o <<= 1) {
            int y = __shfl_up_sync(0xffffffffu, w, o);
            if (lane >= o) w += y;
        }
        wsum[lane] = w;
    }
    __syncthreads();
    int excl = x - v + (wid > 0 ? wsum[wid - 1] : 0);
    if (tid < nb) g_partial[tid] = excl;
}

__global__ void csr_add_offsets(int P) {
    int i = blockIdx.x * blockDim.x + threadIdx.x;
    if (i < P) {
        int o = g_off[i] + g_partial[i >> 12];
        g_off[i] = o;
        g_head[i] = o;
    }
}

__global__ void csr_fill(const int* __restrict__ tri_pair,
                         const int* __restrict__ tri_edge, int T) {
    int i = blockIdx.x * blockDim.x + threadIdx.x;
    if (i < T) {
        int pos = atomicAdd(&g_head[tri_pair[i]], 1);
        g_csr[pos] = tri_edge[i];
    }
}

// ---------------- intra one-pass: logits + ex-weighted message scatter ------
// result_t = (sum_p ex_p * msg_p) / den_t   — division done later.
__global__ void intra_onepass(const int* __restrict__ pair_src, const int* __restrict__ pair_tgt,
                              const float* __restrict__ pair_cnt,
                              const float* __restrict__ ai, int P) {
    int w = (int)(((long)blockIdx.x * blockDim.x + threadIdx.x) >> 5);
    int lane = threadIdx.x & 31;
    if (w >= P) return;
    int s = pair_src[w], t = pair_tgt[w];
    float inv = 1.0f / pair_cnt[w];
    int deg = g_cnt[w];
    int off = g_off[w];

    float u[8], tv[8], m[4];
    load_h8(g_node + (size_t)s * NCC + lane * 8, u);            // S row (+biases)
    load_h8(g_node + (size_t)t * NCC + 256 + lane * 8, tv);     // T row
    load_h4(g_node + (size_t)s * NCC + 768 + lane * 4, m);      // M row (+bmi)
    float ab[8] = {0.f, 0.f, 0.f, 0.f, 0.f, 0.f, 0.f, 0.f};
    float am[4] = {0.f, 0.f, 0.f, 0.f};
    for (int j = 0; j < deg; j++) {
        int e = __ldg(&g_csr[off + j]);
        float bv[8], mv[4];
        load_h8(g_edge + (size_t)e * ECC + lane * 8, bv);       // B row
        load_h4(g_edge + (size_t)e * ECC + 512 + lane * 4, mv); // M row
#pragma unroll
        for (int q = 0; q < 8; q++) ab[q] += bv[q];
#pragma unroll
        for (int q = 0; q < 4; q++) am[q] += mv[q];
    }
    float4 a0 = *(const float4*)(ai + lane * 8);
    float4 a1 = *(const float4*)(ai + lane * 8 + 4);
    float av[8] = {a0.x, a0.y, a0.z, a0.w, a1.x, a1.y, a1.z, a1.w};
    float partial = 0.f;
#pragma unroll
    for (int q = 0; q < 8; q++)
        partial += gelu_exact(u[q] + tv[q] + ab[q] * inv) * av[q];
    // lanes 0-15 -> head 0, lanes 16-31 -> head 1
#pragma unroll
    for (int o = 8; o; o >>= 1) partial += __shfl_down_sync(0xffffffffu, partial, o);
    float l0 = __shfl_sync(0xffffffffu, partial, 0);
    float l1 = __shfl_sync(0xffffffffu, partial, 16);
    float e0 = expf(l0), e1 = expf(l1);
    if (lane == 0) {
        atomicAdd(&g_denomI[t * 2], e0);
        atomicAdd(&g_denomI[t * 2 + 1], e1);
    }
    float exh = (lane >> 4) ? e1 : e0;
    red4(g_accO + (size_t)t * 256 + lane * 4,
         exh * (m[0] + am[0] * inv), exh * (m[1] + am[1] * inv),
         exh * (m[2] + am[2] * inv), exh * (m[3] + am[3] * inv));
}

// ---------------- inter one-pass ---------------------------------------------
__global__ void inter_onepass(const int* __restrict__ inc_edge, const int* __restrict__ inc_node,
                              const float* __restrict__ ae, int E) {
    int w = (int)(((long)blockIdx.x * blockDim.x + threadIdx.x) >> 5);
    int lane = threadIdx.x & 31;
    if (w >= E) return;
    int e = inc_edge[w], n = inc_node[w];
    float u[8], tv[8], m[4];
    load_h8(g_edge + (size_t)e * ECC + 256 + lane * 8, u);      // S(e) row
    load_h8(g_node + (size_t)n * NCC + 512 + lane * 8, tv);     // T2 row (+biases)
    load_h4(g_edge + (size_t)e * ECC + 640 + lane * 4, m);      // Me row (+bme)
    float4 a0 = *(const float4*)(ae + lane * 8);
    float4 a1 = *(const float4*)(ae + lane * 8 + 4);
    float av[8] = {a0.x, a0.y, a0.z, a0.w, a1.x, a1.y, a1.z, a1.w};
    float partial = 0.f;
#pragma unroll
    for (int q = 0; q < 8; q++)
        partial += gelu_exact(u[q] + tv[q]) * av[q];
#pragma unroll
    for (int o = 8; o; o >>= 1) partial += __shfl_down_sync(0xffffffffu, partial, o);
    float l0 = __shfl_sync(0xffffffffu, partial, 0);
    float l1 = __shfl_sync(0xffffffffu, partial, 16);
    float e0 = expf(l0), e1 = expf(l1);
    if (lane == 0) {
        atomicAdd(&g_denomE[n * 2], e0);
        atomicAdd(&g_denomE[n * 2 + 1], e1);
    }
    float exh = (lane >> 4) ? e1 : e0;
    red4(g_accO + (size_t)n * 256 + 128 + lane * 4,
         exh * m[0], exh * m[1], exh * m[2], exh * m[3]);
}

// ---------------- divide accumulators by softmax denominators ----------------
__global__ void divide_acc(int N) {
    int i = blockIdx.x * blockDim.x + threadIdx.x;   // float4 index over [N][64]
    if (i >= N * 64) return;
    int t = i >> 6;
    int col = (i & 63) * 4;                          // 0..252
    float den = (col < 128) ? g_denomI[t * 2 + (col >> 6)]
                            : g_denomE[t * 2 + ((col - 128) >> 6)];
    float inv = (den > 0.f) ? 1.0f / den : 0.f;
    float4 v = ((float4*)g_accO)[i];
    v.x *= inv; v.y *= inv; v.z *= inv; v.w *= inv;
    ((float4*)g_accO)[i] = v;
}

// ---------------- launch ----------------
extern "C" void kernel_launch(void* const* d_in, const int* in_sizes, int n_in,
                              void* d_out, int out_size) {
    const float* node_feat = (const float*)d_in[0];
    const float* edge_feat = (const float*)d_in[1];
    const int*   inc_node  = (const int*)d_in[2];
    const int*   inc_edge  = (const int*)d_in[3];
    const int*   pair_src  = (const int*)d_in[4];
    const int*   pair_tgt  = (const int*)d_in[5];
    const float* pair_cnt  = (const float*)d_in[6];
    const int*   tri_pair  = (const int*)d_in[7];
    const int*   tri_edge  = (const int*)d_in[8];
    const float* Wsi = (const float*)d_in[9];
    const float* bsi = (const float*)d_in[10];
    const float* Wti = (const float*)d_in[11];
    const float* bti = (const float*)d_in[12];
    const float* Wbi = (const float*)d_in[13];
    const float* bbi = (const float*)d_in[14];
    const float* ai  = (const float*)d_in[15];
    const float* Wmi = (const float*)d_in[16];
    const float* bmi = (const float*)d_in[17];
    const float* Woi = (const float*)d_in[18];
    const float* boi = (const float*)d_in[19];
    const float* Wse = (const float*)d_in[20];
    const float* bse = (const float*)d_in[21];
    const float* Wte = (const float*)d_in[22];
    const float* bte = (const float*)d_in[23];
    const float* ae  = (const float*)d_in[24];
    const float* Wme = (const float*)d_in[25];
    const float* bme = (const float*)d_in[26];
    const float* Woe = (const float*)d_in[27];
    const float* boe = (const float*)d_in[28];

    const int N = in_sizes[0] / 128;
    const int M = in_sizes[1] / 128;
    const int E = in_sizes[2];
    const int P = in_sizes[4];
    const int T = in_sizes[7];
    if (N > NMAX || M > MMAX || E > EMAX || P > PMAX || T > TMAX) return;

    void *pNode, *pEdge, *pAccO, *pWn, *pWe, *pWo, *pBn, *pBe, *pBo, *pDenI, *pDenE, *pCnt;
    cudaGetSymbolAddress(&pNode, g_node);
    cudaGetSymbolAddress(&pEdge, g_edge);
    cudaGetSymbolAddress(&pAccO, g_accO);
    cudaGetSymbolAddress(&pWn, g_Wn);
    cudaGetSymbolAddress(&pWe, g_We);
    cudaGetSymbolAddress(&pWo, g_Wo);
    cudaGetSymbolAddress(&pBn, g_bn);
    cudaGetSymbolAddress(&pBe, g_be);
    cudaGetSymbolAddress(&pBo, g_bo);
    cudaGetSymbolAddress(&pDenI, g_denomI);
    cudaGetSymbolAddress(&pDenE, g_denomE);
    cudaGetSymbolAddress(&pCnt, g_cnt);

    cudaFuncSetAttribute(gemm_tf32_t<true>, cudaFuncAttributeMaxDynamicSharedMemorySize, GEMM_SMEM);
    cudaFuncSetAttribute(gemm_tf32_t<false>, cudaFuncAttributeMaxDynamicSharedMemorySize, GEMM_SMEM);

    float* out = (float*)d_out;

    // 1) zero accumulators, denominators, CSR counters
    cudaMemsetAsync(pAccO, 0, (size_t)N * 256 * sizeof(float), 0);
    cudaMemsetAsync(pDenI, 0, (size_t)N * 2 * sizeof(float), 0);
    cudaMemsetAsync(pDenE, 0, (size_t)N * 2 * sizeof(float), 0);
    cudaMemsetAsync(pCnt, 0, (size_t)P * sizeof(int), 0);

    // 2) pack weights / biases
    pack_weights<<<(128 * NCC + 255) / 256, 256>>>(Wsi, Wti, Wte, Wmi, Wbi, Wse, Wme, Woi, Woe,
                                                   bsi, bti, bbi, bse, bte, bmi, bme, boi, boe);

    // 3) projection GEMMs -> combined fp16 tables (biases baked in)
    gemm_tf32_t<true><<<dim3(NCC / 128, N / 128), 256, GEMM_SMEM>>>(
        node_feat, (const float*)pWn, (const float*)pBn, pNode, 128, NCC);
    gemm_tf32_t<true><<<dim3(ECC / 128, M / 128), 256, GEMM_SMEM>>>(
        edge_feat, (const float*)pWe, (const float*)pBe, pEdge, 128, ECC);

    // 4) CSR build: pair -> bridging edges
    int nbScan = (P + 4095) / 4096;
    csr_hist<<<(T + 255) / 256, 256>>>(tri_pair, T);
    csr_scan_block<<<nbScan, 1024>>>(P);
    csr_scan_partials<<<1, 1024>>>(nbScan);
    csr_add_offsets<<<(P + 255) / 256, 256>>>(P);
    csr_fill<<<(T + 255) / 256, 256>>>(tri_pair, tri_edge, T);

    // 5) one-pass attention (softmax via late division)
    int pb = (int)(((long)P * 32 + 255) / 256);
    intra_onepass<<<pb, 256>>>(pair_src, pair_tgt, pair_cnt, ai, P);
    int eb = (int)(((long)E * 32 + 255) / 256);
    inter_onepass<<<eb, 256>>>(inc_edge, inc_node, ae, E);

    // 6) divide by denominators
    divide_acc<<<(N * 64 + 255) / 256, 256>>>(N);

    // 7) fused output projection: out = [accI/denI | accE/denE] @ [Woi;Woe] + (boi+boe)
    gemm_tf32_t<false><<<dim3(1, N / 128), 256, GEMM_SMEM>>>(
        (const float*)pAccO, (const float*)pWo, (const float*)pBo, out, 256, 128);
}

// round 10
// speedup vs baseline: 1.4240x; 1.0545x over previous
#include <cuda_runtime.h>
#include <cuda_fp16.h>

// ---------------- problem constants ----------------
// N=32768, M=8192, D=128, H=128, NH=2 -> hidden 256, HD=64
#define NMAX 32768
#define MMAX 8192
#define EMAX 49152
#define TMAX 294912
#define PMAX (TMAX + NMAX)

// node table cols: [0:256) S(+bsi+bti+bbi) | [256:512) T | [512:768) T2(+bse+bte) | [768:896) M(+bmi)
#define NCC 896
// edge table cols: [0:256) B | [256:512) S | [512:640) M | [640:768) Me(+bme)
#define ECC 768

// ---------------- scratch ----------------
__device__ __half g_node[(size_t)NMAX * NCC];
__device__ __half g_edge[(size_t)MMAX * ECC];
__device__ float  g_accO[(size_t)NMAX * 256];   // [N][256]: intra 0-127, inter 128-255
__device__ __half g_Wn[128 * NCC];
__device__ __half g_We[128 * ECC];
__device__ __half g_Wo[256 * 128];
__device__ float  g_bn[NCC];
__device__ float  g_be[ECC];
__device__ float  g_bo[128];
__device__ float  g_denomI[NMAX * 2];
__device__ float  g_denomE[NMAX * 2];
// CSR: pair -> bridging edges
__device__ int    g_cnt[PMAX];
__device__ int    g_off[PMAX];
__device__ int    g_head[PMAX];
__device__ int    g_csr[TMAX];
__device__ int    g_partial[1024];

// ---------------- helpers ----------------
__device__ __forceinline__ float gelu_exact(float x) {
    return 0.5f * x * (1.0f + erff(x * 0.70710678118654752f));
}
__device__ __forceinline__ void red4(float* addr, float a, float b, float c, float d) {
    asm volatile("red.global.add.v4.f32 [%0], {%1,%2,%3,%4};"
                 :: "l"(addr), "f"(a), "f"(b), "f"(c), "f"(d) : "memory");
}
__device__ __forceinline__ void load_h8(const __half* p, float* f) {
    uint4 r = *(const uint4*)p;
    float2 v;
    v = __half22float2(*(__half2*)&r.x); f[0] = v.x; f[1] = v.y;
    v = __half22float2(*(__half2*)&r.y); f[2] = v.x; f[3] = v.y;
    v = __half22float2(*(__half2*)&r.z); f[4] = v.x; f[5] = v.y;
    v = __half22float2(*(__half2*)&r.w); f[6] = v.x; f[7] = v.y;
}
__device__ __forceinline__ void load_h4(const __half* p, float* f) {
    uint2 r = *(const uint2*)p;
    float2 v;
    v = __half22float2(*(__half2*)&r.x); f[0] = v.x; f[1] = v.y;
    v = __half22float2(*(__half2*)&r.y); f[2] = v.x; f[3] = v.y;
}

// ---------------- weight/bias packing (weights -> fp16) ----------------
__global__ void pack_weights(const float* __restrict__ Wsi, const float* __restrict__ Wti,
                             const float* __restrict__ Wte, const float* __restrict__ Wmi,
                             const float* __restrict__ Wbi, const float* __restrict__ Wse,
                             const float* __restrict__ Wme,
                             const float* __restrict__ Woi, const float* __restrict__ Woe,
                             const float* __restrict__ bsi, const float* __restrict__ bti,
                             const float* __restrict__ bbi, const float* __restrict__ bse,
                             const float* __restrict__ bte, const float* __restrict__ bmi,
                             const float* __restrict__ bme, const float* __restrict__ boi,
                             const float* __restrict__ boe) {
    int i = blockIdx.x * blockDim.x + threadIdx.x;
    if (i < 128 * NCC) {
        int r = i / NCC, c = i % NCC;
        float v;
        if (c < 256) v = Wsi[r * 256 + c];
        else if (c < 512) v = Wti[r * 256 + (c - 256)];
        else if (c < 768) v = Wte[r * 256 + (c - 512)];
        else v = Wmi[r * 128 + (c - 768)];            // Wmi top half
        g_Wn[i] = __float2half(v);
    }
    if (i < 128 * ECC) {
        int r = i / ECC, c = i % ECC;
        float v;
        if (c < 256) v = Wbi[r * 256 + c];
        else if (c < 512) v = Wse[r * 256 + (c - 256)];
        else if (c < 640) v = Wmi[(128 + r) * 128 + (c - 512)];  // Wmi bottom half
        else v = Wme[r * 128 + (c - 640)];
        g_We[i] = __float2half(v);
    }
    if (i < 256 * 128) {
        int r = i / 128, c = i % 128;
        g_Wo[i] = __float2half((r < 128) ? Woi[r * 128 + c] : Woe[(r - 128) * 128 + c]);
    }
    if (i < NCC) {
        float v;
        if (i < 256) v = bsi[i] + bti[i] + bbi[i];
        else if (i < 512) v = 0.f;
        else if (i < 768) v = bse[i - 512] + bte[i - 512];
        else v = bmi[i - 768];
        g_bn[i] = v;
    }
    if (i < ECC) g_be[i] = (i >= 640) ? bme[i - 640] : 0.f;
    if (i < 128) g_bo[i] = boi[i] + boe[i];
}

// ---------------- fp16 tensor-core GEMM, CTA tile 128x128, K-looped ---------
// C[rows,CC] = A[rows,KK](fp32) @ W[KK,CC](fp16) (+bias). m16n8k16 f16/f32-acc.
// As: [128 rows][68 words] half2 along k (word r*68 + k/2). 34816 B.
// Wp: [64 kk][136 words] half2 = (W[2kk][c], W[2kk+1][c]).  34816 B.
#define AS_W 68
#define WP_W 136
#define GEMM_SMEM ((128 * AS_W + 64 * WP_W) * 4)

template <bool HALF_OUT>
__global__ void gemm_fp16_t(const float* __restrict__ A, const __half* __restrict__ W,
                            const float* __restrict__ bias, void* __restrict__ Cv,
                            int KK, int CC) {
    extern __shared__ unsigned sh[];
    unsigned* As = sh;                 // 128*68 words
    unsigned* Wp = sh + 128 * AS_W;    // 64*136 words
    const int tid = threadIdx.x;
    const int lane = tid & 31;
    const int warp = tid >> 5;
    const int wm = warp & 3;           // 4 warps x 32 rows
    const int wn = warp >> 2;          // 2 warps x 64 cols
    const long r0 = (long)blockIdx.y * 128;
    const int  c0 = blockIdx.x * 128;
    const int gid = lane >> 2;
    const int tig = lane & 3;

    float c[2][8][4];
#pragma unroll
    for (int mt = 0; mt < 2; mt++)
#pragma unroll
        for (int nt = 0; nt < 8; nt++)
#pragma unroll
            for (int q = 0; q < 4; q++) c[mt][nt][q] = 0.f;

    for (int kb = 0; kb < KK; kb += 128) {
        if (kb) __syncthreads();
        // stage A chunk [128 rows][128 k] fp32 -> half2 pairs
#pragma unroll
        for (int i = 0; i < 16; i++) {
            int idx = tid + i * 256;       // over [128][32 float4]
            int row = idx >> 5;
            int c4 = idx & 31;
            float4 v = *(const float4*)(A + (r0 + row) * KK + kb + c4 * 4);
            unsigned w0, w1;
            *(__half2*)&w0 = __floats2half2_rn(v.x, v.y);
            *(__half2*)&w1 = __floats2half2_rn(v.z, v.w);
            *(uint2*)(As + row * AS_W + c4 * 2) = make_uint2(w0, w1);
        }
        // stage W chunk [128 k][128 cols] fp16 -> k-paired half2
#pragma unroll
        for (int i = 0; i < 4; i++) {
            int idx = tid + i * 256;       // over [64 kk][16 col-groups of 8]
            int kk = idx >> 4;
            int cg = idx & 15;
            const __half* we = W + (long)(kb + 2 * kk) * CC + c0 + cg * 8;
            uint4 e = *(const uint4*)we;
            uint4 o = *(const uint4*)(we + CC);
            const unsigned short* eh = (const unsigned short*)&e;
            const unsigned short* oh = (const unsigned short*)&o;
            unsigned out[8];
#pragma unroll
            for (int j = 0; j < 8; j++)
                out[j] = (unsigned)eh[j] | ((unsigned)oh[j] << 16);
            unsigned* dst = Wp + kk * WP_W + cg * 8;
            *(uint4*)dst = make_uint4(out[0], out[1], out[2], out[3]);
            *(uint4*)(dst + 4) = make_uint4(out[4], out[5], out[6], out[7]);
        }
        __syncthreads();

        const int arow = wm * 32 + gid;
        const int bcol = wn * 64 + gid;
#pragma unroll
        for (int step = 0; step < 8; step++) {
            int kw0 = step * 8;            // half2-word base for this k16 step
            unsigned a[2][4], b[8][2];
#pragma unroll
            for (int mt = 0; mt < 2; mt++) {
                const unsigned* ap = As + (arow + mt * 16) * AS_W + kw0 + tig;
                a[mt][0] = ap[0];
                a[mt][1] = ap[8 * AS_W];
                a[mt][2] = ap[4];
                a[mt][3] = ap[8 * AS_W + 4];
            }
#pragma unroll
            for (int nt = 0; nt < 8; nt++) {
                b[nt][0] = Wp[(kw0 + tig) * WP_W + bcol + nt * 8];
                b[nt][1] = Wp[(kw0 + tig + 4) * WP_W + bcol + nt * 8];
            }
#pragma unroll
            for (int mt = 0; mt < 2; mt++)
#pragma unroll
                for (int nt = 0; nt < 8; nt++)
                    asm volatile(
                        "mma.sync.aligned.m16n8k16.row.col.f32.f16.f16.f32 "
                        "{%0,%1,%2,%3}, {%4,%5,%6,%7}, {%8,%9}, {%0,%1,%2,%3};"
                        : "+f"(c[mt][nt][0]), "+f"(c[mt][nt][1]),
                          "+f"(c[mt][nt][2]), "+f"(c[mt][nt][3])
                        : "r"(a[mt][0]), "r"(a[mt][1]), "r"(a[mt][2]), "r"(a[mt][3]),
                          "r"(b[nt][0]), "r"(b[nt][1]));
        }
    }

#pragma unroll
    for (int mt = 0; mt < 2; mt++) {
        long r = r0 + wm * 32 + mt * 16 + gid;
#pragma unroll
        for (int nt = 0; nt < 8; nt++) {
            int col = c0 + wn * 64 + nt * 8 + 2 * tig;
            float2 bv = bias ? *(const float2*)(bias + col) : make_float2(0.f, 0.f);
            float x0 = c[mt][nt][0] + bv.x, y0 = c[mt][nt][1] + bv.y;
            float x1 = c[mt][nt][2] + bv.x, y1 = c[mt][nt][3] + bv.y;
            if (HALF_OUT) {
                __half* C = (__half*)Cv;
                *(__half2*)(C + r * CC + col) = __floats2half2_rn(x0, y0);
                *(__half2*)(C + (r + 8) * CC + col) = __floats2half2_rn(x1, y1);
            } else {
                float* C = (float*)Cv;
                *(float2*)(C + r * CC + col) = make_float2(x0, y0);
                *(float2*)(C + (r + 8) * CC + col) = make_float2(x1, y1);
            }
        }
    }
}

// ---------------- CSR build: pair -> bridging edge list ---------------------
__global__ void csr_hist(const int* __restrict__ tri_pair, int T) {
    int i = blockIdx.x * blockDim.x + threadIdx.x;
    if (i < T) atomicAdd(&g_cnt[tri_pair[i]], 1);
}

__global__ void csr_scan_block(int P) {
    __shared__ int wsum[32];
    int tid = threadIdx.x;
    int base = blockIdx.x * 4096 + tid * 4;
    int v[4], s = 0;
#pragma unroll
    for (int q = 0; q < 4; q++) {
        v[q] = (base + q < P) ? g_cnt[base + q] : 0;
        s += v[q];
    }
    int lane = tid & 31, wid = tid >> 5;
    int x = s;
#pragma unroll
    for (int o = 1; o < 32; o <<= 1) {
        int y = __shfl_up_sync(0xffffffffu, x, o);
        if (lane >= o) x += y;
    }
    if (lane == 31) wsum[wid] = x;
    __syncthreads();
    if (wid == 0) {
        int w = wsum[lane];
#pragma unroll
        for (int o = 1; o < 32; o <<= 1) {
            int y = __shfl_up_sync(0xffffffffu, w, o);
            if (lane >= o) w += y;
        }
        wsum[lane] = w;
    }
    __syncthreads();
    int excl = x - s + (wid > 0 ? wsum[wid - 1] : 0);
    int run = excl;
#pragma unroll
    for (int q = 0; q < 4; q++) {
        if (base + q < P) g_off[base + q] = run;
        run += v[q];
    }
    if (tid == 1023) g_partial[blockIdx.x] = wsum[31];
}

__global__ void csr_scan_partials(int nb) {
    __shared__ int wsum[32];
    int tid = threadIdx.x;  // 1024
    int v = (tid < nb) ? g_partial[tid] : 0;
    int lane = tid & 31, wid = tid >> 5;
    int x = v;
#pragma unroll
    for (int o = 1; o < 32; o <<= 1) {
        int y = __shfl_up_sync(0xffffffffu, x, o);
        if (lane >= o) x += y;
    }
    if (lane == 31) wsum[wid] = x;
    __syncthreads();
    if (wid == 0) {
        int w = wsum[lane];
#pragma unroll
        for (int o = 1; o < 32; o <<= 1) {
            int y = __shfl_up_sync(0xffffffffu, w, o);
            if (lane >= o) w += y;
        }
        wsum[lane] = w;
    }
    __syncthreads();
    int excl = x - v + (wid > 0 ? wsum[wid - 1] : 0);
    if (tid < nb) g_partial[tid] = excl;
}

__global__ void csr_add_offsets(int P) {
    int i = blockIdx.x * blockDim.x + threadIdx.x;
    if (i < P) {
        int o = g_off[i] + g_partial[i >> 12];
        g_off[i] = o;
        g_head[i] = o;
    }
}

__global__ void csr_fill(const int* __restrict__ tri_pair,
                         const int* __restrict__ tri_edge, int T) {
    int i = blockIdx.x * blockDim.x + threadIdx.x;
    if (i < T) {
        int pos = atomicAdd(&g_head[tri_pair[i]], 1);
        g_csr[pos] = tri_edge[i];
    }
}

// ---------------- intra one-pass: logits + ex-weighted message scatter ------
__global__ void intra_onepass(const int* __restrict__ pair_src, const int* __restrict__ pair_tgt,
                              const float* __restrict__ pair_cnt,
                              const float* __restrict__ ai, int P) {
    int w = (int)(((long)blockIdx.x * blockDim.x + threadIdx.x) >> 5);
    int lane = threadIdx.x & 31;
    if (w >= P) return;
    int s = pair_src[w], t = pair_tgt[w];
    float inv = 1.0f / pair_cnt[w];
    int deg = g_cnt[w];
    int off = g_off[w];

    float u[8], tv[8], m[4];
    load_h8(g_node + (size_t)s * NCC + lane * 8, u);            // S row (+biases)
    load_h8(g_node + (size_t)t * NCC + 256 + lane * 8, tv);     // T row
    load_h4(g_node + (size_t)s * NCC + 768 + lane * 4, m);      // M row (+bmi)
    float ab[8] = {0.f, 0.f, 0.f, 0.f, 0.f, 0.f, 0.f, 0.f};
    float am[4] = {0.f, 0.f, 0.f, 0.f};
    for (int j = 0; j < deg; j++) {
        int e = __ldg(&g_csr[off + j]);
        float bv[8], mv[4];
        load_h8(g_edge + (size_t)e * ECC + lane * 8, bv);       // B row
        load_h4(g_edge + (size_t)e * ECC + 512 + lane * 4, mv); // M row
#pragma unroll
        for (int q = 0; q < 8; q++) ab[q] += bv[q];
#pragma unroll
        for (int q = 0; q < 4; q++) am[q] += mv[q];
    }
    float4 a0 = *(const float4*)(ai + lane * 8);
    float4 a1 = *(const float4*)(ai + lane * 8 + 4);
    float av[8] = {a0.x, a0.y, a0.z, a0.w, a1.x, a1.y, a1.z, a1.w};
    float partial = 0.f;
#pragma unroll
    for (int q = 0; q < 8; q++)
        partial += gelu_exact(u[q] + tv[q] + ab[q] * inv) * av[q];
#pragma unroll
    for (int o = 8; o; o >>= 1) partial += __shfl_down_sync(0xffffffffu, partial, o);
    float l0 = __shfl_sync(0xffffffffu, partial, 0);
    float l1 = __shfl_sync(0xffffffffu, partial, 16);
    float e0 = expf(l0), e1 = expf(l1);
    if (lane == 0) {
        atomicAdd(&g_denomI[t * 2], e0);
        atomicAdd(&g_denomI[t * 2 + 1], e1);
    }
    float exh = (lane >> 4) ? e1 : e0;
    red4(g_accO + (size_t)t * 256 + lane * 4,
         exh * (m[0] + am[0] * inv), exh * (m[1] + am[1] * inv),
         exh * (m[2] + am[2] * inv), exh * (m[3] + am[3] * inv));
}

// ---------------- inter one-pass ---------------------------------------------
__global__ void inter_onepass(const int* __restrict__ inc_edge, const int* __restrict__ inc_node,
                              const float* __restrict__ ae, int E) {
    int w = (int)(((long)blockIdx.x * blockDim.x + threadIdx.x) >> 5);
    int lane = threadIdx.x & 31;
    if (w >= E) return;
    int e = inc_edge[w], n = inc_node[w];
    float u[8], tv[8], m[4];
    load_h8(g_edge + (size_t)e * ECC + 256 + lane * 8, u);      // S(e) row
    load_h8(g_node + (size_t)n * NCC + 512 + lane * 8, tv);     // T2 row (+biases)
    load_h4(g_edge + (size_t)e * ECC + 640 + lane * 4, m);      // Me row (+bme)
    float4 a0 = *(const float4*)(ae + lane * 8);
    float4 a1 = *(const float4*)(ae + lane * 8 + 4);
    float av[8] = {a0.x, a0.y, a0.z, a0.w, a1.x, a1.y, a1.z, a1.w};
    float partial = 0.f;
#pragma unroll
    for (int q = 0; q < 8; q++)
        partial += gelu_exact(u[q] + tv[q]) * av[q];
#pragma unroll
    for (int o = 8; o; o >>= 1) partial += __shfl_down_sync(0xffffffffu, partial, o);
    float l0 = __shfl_sync(0xffffffffu, partial, 0);
    float l1 = __shfl_sync(0xffffffffu, partial, 16);
    float e0 = expf(l0), e1 = expf(l1);
    if (lane == 0) {
        atomicAdd(&g_denomE[n * 2], e0);
        atomicAdd(&g_denomE[n * 2 + 1], e1);
    }
    float exh = (lane >> 4) ? e1 : e0;
    red4(g_accO + (size_t)n * 256 + 128 + lane * 4,
         exh * m[0], exh * m[1], exh * m[2], exh * m[3]);
}

// ---------------- divide accumulators by softmax denominators ----------------
__global__ void divide_acc(int N) {
    int i = blockIdx.x * blockDim.x + threadIdx.x;   // float4 index over [N][64]
    if (i >= N * 64) return;
    int t = i >> 6;
    int col = (i & 63) * 4;                          // 0..252
    float den = (col < 128) ? g_denomI[t * 2 + (col >> 6)]
                            : g_denomE[t * 2 + ((col - 128) >> 6)];
    float inv = (den > 0.f) ? 1.0f / den : 0.f;
    float4 v = ((float4*)g_accO)[i];
    v.x *= inv; v.y *= inv; v.z *= inv; v.w *= inv;
    ((float4*)g_accO)[i] = v;
}

// ---------------- launch ----------------
extern "C" void kernel_launch(void* const* d_in, const int* in_sizes, int n_in,
                              void* d_out, int out_size) {
    const float* node_feat = (const float*)d_in[0];
    const float* edge_feat = (const float*)d_in[1];
    const int*   inc_node  = (const int*)d_in[2];
    const int*   inc_edge  = (const int*)d_in[3];
    const int*   pair_src  = (const int*)d_in[4];
    const int*   pair_tgt  = (const int*)d_in[5];
    const float* pair_cnt  = (const float*)d_in[6];
    const int*   tri_pair  = (const int*)d_in[7];
    const int*   tri_edge  = (const int*)d_in[8];
    const float* Wsi = (const float*)d_in[9];
    const float* bsi = (const float*)d_in[10];
    const float* Wti = (const float*)d_in[11];
    const float* bti = (const float*)d_in[12];
    const float* Wbi = (const float*)d_in[13];
    const float* bbi = (const float*)d_in[14];
    const float* ai  = (const float*)d_in[15];
    const float* Wmi = (const float*)d_in[16];
    const float* bmi = (const float*)d_in[17];
    const float* Woi = (const float*)d_in[18];
    const float* boi = (const float*)d_in[19];
    const float* Wse = (const float*)d_in[20];
    const float* bse = (const float*)d_in[21];
    const float* Wte = (const float*)d_in[22];
    const float* bte = (const float*)d_in[23];
    const float* ae  = (const float*)d_in[24];
    const float* Wme = (const float*)d_in[25];
    const float* bme = (const float*)d_in[26];
    const float* Woe = (const float*)d_in[27];
    const float* boe = (const float*)d_in[28];

    const int N = in_sizes[0] / 128;
    const int M = in_sizes[1] / 128;
    const int E = in_sizes[2];
    const int P = in_sizes[4];
    const int T = in_sizes[7];
    if (N > NMAX || M > MMAX || E > EMAX || P > PMAX || T > TMAX) return;

    void *pNode, *pEdge, *pAccO, *pWn, *pWe, *pWo, *pBn, *pBe, *pBo, *pDenI, *pDenE, *pCnt;
    cudaGetSymbolAddress(&pNode, g_node);
    cudaGetSymbolAddress(&pEdge, g_edge);
    cudaGetSymbolAddress(&pAccO, g_accO);
    cudaGetSymbolAddress(&pWn, g_Wn);
    cudaGetSymbolAddress(&pWe, g_We);
    cudaGetSymbolAddress(&pWo, g_Wo);
    cudaGetSymbolAddress(&pBn, g_bn);
    cudaGetSymbolAddress(&pBe, g_be);
    cudaGetSymbolAddress(&pBo, g_bo);
    cudaGetSymbolAddress(&pDenI, g_denomI);
    cudaGetSymbolAddress(&pDenE, g_denomE);
    cudaGetSymbolAddress(&pCnt, g_cnt);

    cudaFuncSetAttribute(gemm_fp16_t<true>, cudaFuncAttributeMaxDynamicSharedMemorySize, GEMM_SMEM);
    cudaFuncSetAttribute(gemm_fp16_t<false>, cudaFuncAttributeMaxDynamicSharedMemorySize, GEMM_SMEM);

    float* out = (float*)d_out;

    // 1) zero accumulators, denominators, CSR counters
    cudaMemsetAsync(pAccO, 0, (size_t)N * 256 * sizeof(float), 0);
    cudaMemsetAsync(pDenI, 0, (size_t)N * 2 * sizeof(float), 0);
    cudaMemsetAsync(pDenE, 0, (size_t)N * 2 * sizeof(float), 0);
    cudaMemsetAsync(pCnt, 0, (size_t)P * sizeof(int), 0);

    // 2) pack weights (fp16) / biases (fp32)
    pack_weights<<<(128 * NCC + 255) / 256, 256>>>(Wsi, Wti, Wte, Wmi, Wbi, Wse, Wme, Woi, Woe,
                                                   bsi, bti, bbi, bse, bte, bmi, bme, boi, boe);

    // 3) projection GEMMs (fp16 MMA) -> combined fp16 tables (biases baked in)
    gemm_fp16_t<true><<<dim3(NCC / 128, N / 128), 256, GEMM_SMEM>>>(
        node_feat, (const __half*)pWn, (const float*)pBn, pNode, 128, NCC);
    gemm_fp16_t<true><<<dim3(ECC / 128, M / 128), 256, GEMM_SMEM>>>(
        edge_feat, (const __half*)pWe, (const float*)pBe, pEdge, 128, ECC);

    // 4) CSR build: pair -> bridging edges
    int nbScan = (P + 4095) / 4096;
    csr_hist<<<(T + 255) / 256, 256>>>(tri_pair, T);
    csr_scan_block<<<nbScan, 1024>>>(P);
    csr_scan_partials<<<1, 1024>>>(nbScan);
    csr_add_offsets<<<(P + 255) / 256, 256>>>(P);
    csr_fill<<<(T + 255) / 256, 256>>>(tri_pair, tri_edge, T);

    // 5) one-pass attention (softmax via late division)
    int pb = (int)(((long)P * 32 + 255) / 256);
    intra_onepass<<<pb, 256>>>(pair_src, pair_tgt, pair_cnt, ai, P);
    int eb = (int)(((long)E * 32 + 255) / 256);
    inter_onepass<<<eb, 256>>>(inc_edge, inc_node, ae, E);

    // 6) divide by denominators
    divide_acc<<<(N * 64 + 255) / 256, 256>>>(N);

    // 7) fused output projection: out = [accI/denI | accE/denE] @ [Woi;Woe] + (boi+boe)
    gemm_fp16_t<false><<<dim3(1, N / 128), 256, GEMM_SMEM>>>(
        (const float*)pAccO, (const __half*)pWo, (const float*)pBo, out, 256, 128);
}